// round 3
// baseline (speedup 1.0000x reference)
#include <cuda_runtime.h>
#include <math.h>
#include <stdint.h>

// Problem dims
#define BB   64
#define TT   512
#define DD   256
#define HH   1024
#define LL   256
#define OO   256
#define KTOT 1536        // D (x) + L (s) + H (h)
#define KC   32          // K chunk
#define NCH  (KTOT/KC)   // 48 chunks
#define GRID 128
#define BLK  128

// Persistent state (no allocations allowed)
__device__ float g_h[2][BB*HH];   // double-buffered hidden state
__device__ float g_c[BB*HH];      // cell state (partitioned per CTA -> single buffer ok)
__device__ float g_s[BB*LL];      // latent state (single buffer ok, see barrier proof)
__device__ unsigned g_count;      // grid barrier counter

__global__ void reset_kernel() {
    int i = blockIdx.x * blockDim.x + threadIdx.x;
    if (i == 0) g_count = 0u;
    if (i < BB*HH) { g_h[0][i] = 0.f; g_c[i] = 0.f; }
    if (i < BB*LL) g_s[i] = 0.f;
}

__device__ __forceinline__ void fma4(float4& a, float s, const float4& v) {
    a.x = fmaf(s, v.x, a.x);
    a.y = fmaf(s, v.y, a.y);
    a.z = fmaf(s, v.z, a.z);
    a.w = fmaf(s, v.w, a.w);
}
__device__ __forceinline__ float sigm(float x) { return 1.f / (1.f + expf(-x)); }

// Monotonic-target grid barrier. Writers do __threadfence before arriving;
// reader spins on volatile load, fence after for acquire semantics.
__device__ __forceinline__ void gridbar(unsigned target) {
    __syncthreads();
    if (threadIdx.x == 0) {
        __threadfence();
        atomicAdd(&g_count, 1u);
        while (*((volatile unsigned*)&g_count) < target) { __nanosleep(64); }
        __threadfence();
    }
    __syncthreads();
}

// Shared memory layout (floats):
//   sW: [KC][36]  (W tile, k-major, padded to 36 so rows are 16B-aligned)
//   sI: [KC][68]  (inp tile, k-major, padded to 68 for alignment)
//   sG: [32][68]  aliases the front of the arena (used after the K loop)
#define SW_STRIDE 36
#define SI_STRIDE 68
#define SG_STRIDE 68
#define SMEM_FLOATS (KC*SW_STRIDE + KC*SI_STRIDE)

struct PrefW { int row, kq, jg; };
struct PrefI { int b, kq; };

__device__ __forceinline__ void prefetch_chunk(
    int k0, int t,
    const float* __restrict__ x, const float* __restrict__ Wih,
    const float* __restrict__ Whh, const float* __restrict__ hread,
    const PrefW pw[2], const PrefI pi[4],
    float4 wreg[2], float4 ireg[4])
{
#pragma unroll
    for (int r = 0; r < 2; r++) {
        int k = k0 + pw[r].kq;
        const float* src = (k < 512) ? (Wih + pw[r].jg * 512 + k)
                                     : (Whh + pw[r].jg * 1024 + (k - 512));
        wreg[r] = *(const float4*)src;
    }
#pragma unroll
    for (int r = 0; r < 4; r++) {
        int k = k0 + pi[r].kq;
        const float* src;
        if (k < 256)      src = x + ((size_t)pi[r].b * TT + t) * DD + k;
        else if (k < 512) src = g_s + pi[r].b * LL + (k - 256);
        else              src = hread + pi[r].b * HH + (k - 512);
        ireg[r] = *(const float4*)src;
    }
}

__global__ void __launch_bounds__(BLK)
lstm_persistent(
    const float* __restrict__ x,
    const float* __restrict__ Wih,  const float* __restrict__ Whh,
    const float* __restrict__ bih,  const float* __restrict__ bhh,
    const float* __restrict__ Wenc, const float* __restrict__ benc,
    const float* __restrict__ Wpred,const float* __restrict__ bpred,
    const float* __restrict__ Wact, const float* __restrict__ bact,
    float* __restrict__ out)
{
    __shared__ float sm[SMEM_FLOATS];
    float* sW = sm;                  // [KC][36]
    float* sI = sm + KC * SW_STRIDE; // [KC][68]
    float* sG = sm;                  // [32][68] alias (valid after K loop)

    const int tid  = threadIdx.x;
    const int lane = tid & 31;
    const int warp = tid >> 5;
    const int tj   = tid >> 4;   // 0..7 -> 4 j-rows each
    const int tb   = tid & 15;   // 0..15 -> 4 batches each
    const int u0   = blockIdx.x * 8;

    float* outY = out;
    float* outS = out + (size_t)BB * TT * OO;
    float* outP = out + (size_t)2 * BB * TT * OO;

    // Prefetch descriptors (constant over t)
    PrefW pw[2];
#pragma unroll
    for (int r = 0; r < 2; r++) {
        int i = tid + 128 * r;
        pw[r].row = i >> 3;
        pw[r].kq  = (i & 7) * 4;
        pw[r].jg  = ((pw[r].row >> 3) << 10) + u0 + (pw[r].row & 7);
    }
    PrefI pi[4];
#pragma unroll
    for (int r = 0; r < 4; r++) {
        int i = tid + 128 * r;
        pi[r].b  = i >> 3;
        pi[r].kq = (i & 7) * 4;
    }

    unsigned bt = 0;

    for (int t = 0; t < TT; ++t) {
        const int ping = t & 1;
        const float* hread  = g_h[ping];
        float*       hwrite = g_h[ping ^ 1];

        // ---------------- Phase A: gates GEMM [32j x 64b], K=1536 ----------
        float4 acc0 = {0,0,0,0}, acc1 = {0,0,0,0}, acc2 = {0,0,0,0}, acc3 = {0,0,0,0};
        float4 wreg[2], ireg[4];

        prefetch_chunk(0, t, x, Wih, Whh, hread, pw, pi, wreg, ireg);

        for (int c = 0; c < NCH; ++c) {
            __syncthreads();   // previous compute done, smem free
            // store staged regs transposed into smem
#pragma unroll
            for (int r = 0; r < 2; r++) {
                int base = pw[r].kq * SW_STRIDE + pw[r].row;
                sW[base + 0*SW_STRIDE] = wreg[r].x;
                sW[base + 1*SW_STRIDE] = wreg[r].y;
                sW[base + 2*SW_STRIDE] = wreg[r].z;
                sW[base + 3*SW_STRIDE] = wreg[r].w;
            }
#pragma unroll
            for (int r = 0; r < 4; r++) {
                int base = pi[r].kq * SI_STRIDE + pi[r].b;
                sI[base + 0*SI_STRIDE] = ireg[r].x;
                sI[base + 1*SI_STRIDE] = ireg[r].y;
                sI[base + 2*SI_STRIDE] = ireg[r].z;
                sI[base + 3*SI_STRIDE] = ireg[r].w;
            }
            __syncthreads();
            if (c + 1 < NCH)   // overlap next chunk's LDG with compute
                prefetch_chunk((c + 1) * KC, t, x, Wih, Whh, hread, pw, pi, wreg, ireg);
#pragma unroll
            for (int k = 0; k < KC; k++) {
                float4 w4 = *(const float4*)&sW[k * SW_STRIDE + 4 * tj];
                float4 i4 = *(const float4*)&sI[k * SI_STRIDE + 4 * tb];
                fma4(acc0, w4.x, i4);
                fma4(acc1, w4.y, i4);
                fma4(acc2, w4.z, i4);
                fma4(acc3, w4.w, i4);
            }
        }

        __syncthreads();
        // add bias, park gates in sG[32][68]
        {
            float4 a[4] = {acc0, acc1, acc2, acc3};
#pragma unroll
            for (int aa = 0; aa < 4; ++aa) {
                int rr = 4 * tj + aa;
                int j  = ((rr >> 3) << 10) + u0 + (rr & 7);
                float bsum = bih[j] + bhh[j];
                float4 v = a[aa];
                v.x += bsum; v.y += bsum; v.z += bsum; v.w += bsum;
                *(float4*)&sG[rr * SG_STRIDE + 4 * tb] = v;
            }
        }
        __syncthreads();

        // LSTM elementwise: 8 units x 64 batches, 4 items per thread
#pragma unroll
        for (int r = 0; r < 4; r++) {
            int idx = tid + 128 * r;          // 0..511
            int uu  = idx >> 6;               // 0..7
            int b   = idx & 63;
            int u   = u0 + uu;
            float ig = sigm (sG[(uu     ) * SG_STRIDE + b]);
            float fg = sigm (sG[( 8 + uu) * SG_STRIDE + b]);
            float gg = tanhf(sG[(16 + uu) * SG_STRIDE + b]);
            float og = sigm (sG[(24 + uu) * SG_STRIDE + b]);
            float cn = fg * g_c[b * HH + u] + ig * gg;
            float hn = og * tanhf(cn);
            g_c[b * HH + u]   = cn;
            hwrite[b * HH + u] = hn;
        }

        bt += GRID; gridbar(bt);

        // ---------------- Phase B: s_curr = tanh(h_new @ Wenc^T + benc) ----
        {
            const float* hn = hwrite;
            int l0 = blockIdx.x * 2;
            const float4* w0 = (const float4*)(Wenc + (size_t)l0 * HH);
            const float4* w1 = (const float4*)(Wenc + (size_t)(l0 + 1) * HH);
            for (int b = warp; b < BB; b += 4) {
                const float4* hp = (const float4*)(hn + b * HH);
                float a0 = 0.f, a1 = 0.f;
#pragma unroll
                for (int it = 0; it < 8; ++it) {
                    float4 hv = hp[it * 32 + lane];
                    float4 wa = w0[it * 32 + lane];
                    float4 wb = w1[it * 32 + lane];
                    a0 += hv.x*wa.x + hv.y*wa.y + hv.z*wa.z + hv.w*wa.w;
                    a1 += hv.x*wb.x + hv.y*wb.y + hv.z*wb.z + hv.w*wb.w;
                }
#pragma unroll
                for (int o = 16; o; o >>= 1) {
                    a0 += __shfl_xor_sync(0xffffffffu, a0, o);
                    a1 += __shfl_xor_sync(0xffffffffu, a1, o);
                }
                if (lane == 0) {
                    float s0 = tanhf(a0 + benc[l0]);
                    float s1 = tanhf(a1 + benc[l0 + 1]);
                    g_s[b * LL + l0]     = s0;
                    g_s[b * LL + l0 + 1] = s1;
                    size_t o0 = ((size_t)b * TT + t) * LL;
                    outS[o0 + l0]     = s0;
                    outS[o0 + l0 + 1] = s1;
                }
            }
        }

        bt += GRID; gridbar(bt);

        // ---------------- Phase C: y = s@Wact^T+b ; s_pred = tanh(s@Wpred^T+b)
        // (reads only s_curr; next writers to g_s are behind the next barrier)
        {
            int r0 = blockIdx.x * 2;
            const float4* wa0 = (const float4*)(Wact  + (size_t)r0 * LL);
            const float4* wa1 = (const float4*)(Wact  + (size_t)(r0 + 1) * LL);
            const float4* wp0 = (const float4*)(Wpred + (size_t)r0 * LL);
            const float4* wp1 = (const float4*)(Wpred + (size_t)(r0 + 1) * LL);
            for (int b = warp; b < BB; b += 4) {
                const float4* sp = (const float4*)(g_s + b * LL);
                float y0 = 0.f, y1 = 0.f, p0 = 0.f, p1 = 0.f;
#pragma unroll
                for (int it = 0; it < 2; ++it) {
                    float4 sv = sp[it * 32 + lane];
                    float4 v0 = wa0[it * 32 + lane];
                    float4 v1 = wa1[it * 32 + lane];
                    float4 v2 = wp0[it * 32 + lane];
                    float4 v3 = wp1[it * 32 + lane];
                    y0 += sv.x*v0.x + sv.y*v0.y + sv.z*v0.z + sv.w*v0.w;
                    y1 += sv.x*v1.x + sv.y*v1.y + sv.z*v1.z + sv.w*v1.w;
                    p0 += sv.x*v2.x + sv.y*v2.y + sv.z*v2.z + sv.w*v2.w;
                    p1 += sv.x*v3.x + sv.y*v3.y + sv.z*v3.z + sv.w*v3.w;
                }
#pragma unroll
                for (int o = 16; o; o >>= 1) {
                    y0 += __shfl_xor_sync(0xffffffffu, y0, o);
                    y1 += __shfl_xor_sync(0xffffffffu, y1, o);
                    p0 += __shfl_xor_sync(0xffffffffu, p0, o);
                    p1 += __shfl_xor_sync(0xffffffffu, p1, o);
                }
                if (lane == 0) {
                    size_t o0 = ((size_t)b * TT + t) * OO;
                    outY[o0 + r0]     = y0 + bact[r0];
                    outY[o0 + r0 + 1] = y1 + bact[r0 + 1];
                    outP[o0 + r0]     = tanhf(p0 + bpred[r0]);
                    outP[o0 + r0 + 1] = tanhf(p1 + bpred[r0 + 1]);
                }
            }
        }
        // No barrier needed here: the next write to g_s (Phase B of t+1) and
        // to hread's buffer (Phase A of t+1 writes the *other* buffer) are
        // ordered behind gridbar(t+1, phase A->B).
    }
}

extern "C" void kernel_launch(void* const* d_in, const int* in_sizes, int n_in,
                              void* d_out, int out_size)
{
    const float* x     = (const float*)d_in[0];   // [64,512,256]
    const float* Wih   = (const float*)d_in[1];   // [4096,512]
    const float* Whh   = (const float*)d_in[2];   // [4096,1024]
    const float* bih   = (const float*)d_in[3];   // [4096]
    const float* bhh   = (const float*)d_in[4];   // [4096]
    const float* Wenc  = (const float*)d_in[5];   // [256,1024]
    const float* benc  = (const float*)d_in[6];   // [256]
    const float* Wpred = (const float*)d_in[7];   // [256,256]
    const float* bpred = (const float*)d_in[8];   // [256]
    const float* Wact  = (const float*)d_in[9];   // [256,256]
    const float* bact  = (const float*)d_in[10];  // [256]
    float* out = (float*)d_out;                   // [y | states | preds]

    (void)in_sizes; (void)n_in; (void)out_size;

    reset_kernel<<<256, 256>>>();
    lstm_persistent<<<GRID, BLK>>>(x, Wih, Whh, bih, bhh,
                                   Wenc, benc, Wpred, bpred, Wact, bact, out);
}